// round 10
// baseline (speedup 1.0000x reference)
#include <cuda_runtime.h>
#include <math.h>

#define B 64
#define CHI 20
#define D 65536                 // 64*32*32 floats per frame
#define D4 (D / 4)

#define NGROUPS 16              // concurrent batches (16 * 5.24 MB = 84 MB < L2)
#define GBLK 64                 // blocks per group  (grid = 1024, single wave @ 7/SM)
#define NITER (B / NGROUPS)     // 4 batches per group, sequential
#define NBLK (NGROUPS * GBLK)   // 1024 blocks
#define TILES2 (D / (GBLK * 256))  // 4 phase-2 sub-tiles per block

__device__ float g_partial[B * CHI * GBLK];     // per-block partial dots
__device__ unsigned g_bar[NGROUPS * NITER];     // group barrier counters

__global__ void init_kernel() {
    if (threadIdx.x < NGROUPS * NITER) g_bar[threadIdx.x] = 0u;
}

// ---------------------------------------------------------------------------
// Fused persistent kernel. Group g (GBLK blocks) processes batches
// b = it*NGROUPS + g:
//   phase 1: score partials over this block's D/64 slice (coalesced float4)
//   group barrier (all 1024 blocks co-resident: 8 blk/SM capacity >= 7 needed)
//   softmax recomputed per block from partials (L2-hot)
//   phase 2: out[b,d] = sum_c x_flat[b, d*CHI + c] * alpha[c] via SMEM staging
//            (reads the batch that phase 1 just installed in L2)
// ---------------------------------------------------------------------------
__global__ __launch_bounds__(256, 7) void fused_kernel(const float* __restrict__ x,
                                                       float* __restrict__ out) {
    const int g   = blockIdx.x / GBLK;
    const int j   = blockIdx.x % GBLK;
    const int tid = threadIdx.x;
    const int warp = tid >> 5;
    const int lane = tid & 31;

    __shared__ float4 s4[256 * CHI / 4];   // 20 KB staging
    __shared__ float sred[CHI][8];
    __shared__ float s_alpha[CHI];

    for (int it = 0; it < NITER; it++) {
        const int b = it * NGROUPS + g;
        const float* __restrict__ xb = x + (size_t)b * CHI * D;

        // ------------------ phase 1: score partials (1 float4/thread/frame) --
        const float4* __restrict__ xb4 =
            reinterpret_cast<const float4*>(xb) + (size_t)j * 256;

        const float4 l = xb4[(size_t)(CHI - 1) * D4 + tid];
        float acc[CHI];
        #pragma unroll
        for (int c = 0; c < CHI - 1; c++) {
            const float4 f = xb4[(size_t)c * D4 + tid];
            acc[c] = fmaf(f.x, l.x, fmaf(f.y, l.y,
                     fmaf(f.z, l.z, f.w * l.w)));
        }
        acc[CHI - 1] = fmaf(l.x, l.x, fmaf(l.y, l.y,
                       fmaf(l.z, l.z, l.w * l.w)));

        #pragma unroll
        for (int c = 0; c < CHI; c++) {
            #pragma unroll
            for (int o = 16; o; o >>= 1)
                acc[c] += __shfl_xor_sync(0xFFFFFFFFu, acc[c], o);
        }
        if (lane == 0) {
            #pragma unroll
            for (int c = 0; c < CHI; c++) sred[c][warp] = acc[c];
        }
        __syncthreads();
        if (tid < CHI) {
            float v = 0.0f;
            #pragma unroll
            for (int w = 0; w < 8; w++) v += sred[tid][w];
            g_partial[(b * CHI + tid) * GBLK + j] = v;
        }
        __threadfence();           // release partials
        __syncthreads();

        // ------------------ group barrier ------------------
        if (tid == 0) {
            unsigned* ctr = &g_bar[g * NITER + it];
            atomicAdd(ctr, 1u);
            while (*(volatile unsigned*)ctr < (unsigned)GBLK) __nanosleep(64);
            __threadfence();       // acquire
        }
        __syncthreads();

        // ------------------ softmax (warp 0, then broadcast) ------------------
        if (warp == 0) {
            float s = -INFINITY;
            if (lane < CHI) {
                const float4* p = reinterpret_cast<const float4*>(
                    &g_partial[(b * CHI + lane) * GBLK]);
                float t = 0.0f;
                #pragma unroll
                for (int k = 0; k < GBLK / 4; k++) {
                    const float4 v = p[k];
                    t += (v.x + v.y) + (v.z + v.w);
                }
                s = t * (1.0f / CHI);
            }
            float m = s;
            #pragma unroll
            for (int o = 16; o; o >>= 1)
                m = fmaxf(m, __shfl_xor_sync(0xFFFFFFFFu, m, o));
            float e = (lane < CHI) ? expf(s - m) : 0.0f;
            float sum = e;
            #pragma unroll
            for (int o = 16; o; o >>= 1)
                sum += __shfl_xor_sync(0xFFFFFFFFu, sum, o);
            if (lane < CHI) s_alpha[lane] = e / sum;
        }
        __syncthreads();

        float a[CHI];
        #pragma unroll
        for (int c = 0; c < CHI; c++) a[c] = s_alpha[c];

        // ------------------ phase 2: out (L2-hot read) ------------------
        #pragma unroll 1
        for (int t = 0; t < TILES2; t++) {        // 4 sub-tiles of 256 d's
            const int dbase = (j * TILES2 + t) * 256;
            const float4* __restrict__ src =
                reinterpret_cast<const float4*>(xb + (size_t)dbase * CHI);
            #pragma unroll
            for (int i = 0; i < 5; i++)
                s4[i * 256 + tid] = src[i * 256 + tid];
            __syncthreads();

            const float4* mine = s4 + tid * 5;    // 20 contiguous floats
            float o_ = 0.0f;
            #pragma unroll
            for (int i = 0; i < 5; i++) {
                const float4 v = mine[i];
                o_ = fmaf(v.x, a[4 * i + 0], fmaf(v.y, a[4 * i + 1],
                     fmaf(v.z, a[4 * i + 2], fmaf(v.w, a[4 * i + 3], o_))));
            }
            out[(size_t)b * D + dbase + tid] = o_;
            __syncthreads();
        }
    }
}

extern "C" void kernel_launch(void* const* d_in, const int* in_sizes, int n_in,
                              void* d_out, int out_size) {
    const float* x = (const float*)d_in[0];
    float* out = (float*)d_out;

    init_kernel<<<1, 64>>>();
    fused_kernel<<<NBLK, 256>>>(x, out);
}

// round 14
// speedup vs baseline: 1.2134x; 1.2134x over previous
#include <cuda_runtime.h>
#include <math.h>

#define B 64
#define CHI 20
#define D 65536                 // 64*32*32 floats per frame
#define D4 (D / 4)

#define NGROUPS 8               // concurrent groups; 2 in-flight batches each = 84MB < L2
#define GBLK 64                 // blocks per group
#define NITER (B / NGROUPS)     // 8 batches per group
#define NBLK (NGROUPS * GBLK)   // 512 blocks; 4/SM capacity -> all co-resident
#define CGRP 5                  // c's per phase-1 sub-step (5 accumulators only)
#define NCG (CHI / CGRP)        // 4 sub-steps, interleaved with 4 phase-2 tiles
#define TILES2 (D / GBLK / 256) // 4 phase-2 tiles of 256 d's per block

__device__ float g_partial[B * CHI * GBLK];
__device__ unsigned g_bar[NGROUPS * NITER];

__global__ void init_kernel() {
    if (threadIdx.x < NGROUPS * NITER) g_bar[threadIdx.x] = 0u;
}

// softmax over g_partial[b] -> s_alpha (warp 0 computes, block syncs after)
__device__ __forceinline__ void softmax_to_smem(int b, float* s_alpha,
                                                int warp, int lane) {
    if (warp == 0) {
        float s = -INFINITY;
        if (lane < CHI) {
            const float4* p = reinterpret_cast<const float4*>(
                &g_partial[(b * CHI + lane) * GBLK]);
            float t = 0.0f;
            #pragma unroll
            for (int k = 0; k < GBLK / 4; k++) {
                const float4 v = p[k];
                t += (v.x + v.y) + (v.z + v.w);
            }
            s = t * (1.0f / CHI);
        }
        float m = s;
        #pragma unroll
        for (int o = 16; o; o >>= 1)
            m = fmaxf(m, __shfl_xor_sync(0xFFFFFFFFu, m, o));
        float e = (lane < CHI) ? expf(s - m) : 0.0f;
        float sum = e;
        #pragma unroll
        for (int o = 16; o; o >>= 1)
            sum += __shfl_xor_sync(0xFFFFFFFFu, sum, o);
        if (lane < CHI) s_alpha[lane] = e / sum;
    }
    __syncthreads();
}

// one phase-2 tile: out[b2, dbase..dbase+255] via SMEM staging (L2-hot read)
__device__ __forceinline__ void p2_tile(const float* __restrict__ xb2,
                                        float* __restrict__ out, int b2,
                                        int dbase, float4* s4,
                                        const float* s_alpha, int tid) {
    const float4* __restrict__ src =
        reinterpret_cast<const float4*>(xb2 + (size_t)dbase * CHI);
    #pragma unroll
    for (int i = 0; i < 5; i++)
        s4[i * 256 + tid] = src[i * 256 + tid];
    __syncthreads();

    const float4* mine = s4 + tid * 5;    // 20 contiguous floats for this d
    float o_ = 0.0f;
    #pragma unroll
    for (int i = 0; i < 5; i++) {
        const float4 v = mine[i];
        o_ = fmaf(v.x, s_alpha[4 * i + 0], fmaf(v.y, s_alpha[4 * i + 1],
             fmaf(v.z, s_alpha[4 * i + 2], fmaf(v.w, s_alpha[4 * i + 3], o_))));
    }
    out[(size_t)b2 * D + dbase + tid] = o_;
    __syncthreads();
}

// ---------------------------------------------------------------------------
// Fused pipelined persistent kernel. Group g (64 blocks) per iteration `it`:
//   interleave { P2 tile k for batch b_it-1 (L2-hit) ; P1 c-group k for b_it
//   (DRAM stream) } x4, publish partials, group barrier. DRAM and L2 streams
//   overlap throughout; each batch is read from DRAM exactly once.
// ---------------------------------------------------------------------------
__global__ __launch_bounds__(256, 4) void fused_kernel(const float* __restrict__ x,
                                                       float* __restrict__ out) {
    const int g    = blockIdx.x / GBLK;
    const int j    = blockIdx.x % GBLK;
    const int tid  = threadIdx.x;
    const int warp = tid >> 5;
    const int lane = tid & 31;

    __shared__ float4 s4[256 * CHI / 4];   // 20 KB staging
    __shared__ float sred[CHI][8];
    __shared__ float s_alpha[CHI];

    for (int it = 0; it < NITER; it++) {
        const int b1 = it * NGROUPS + g;               // phase-1 batch
        const int b2 = b1 - NGROUPS;                   // phase-2 batch (prev iter)
        const float* __restrict__ xb1 = x + (size_t)b1 * CHI * D;
        const float* __restrict__ xb2 =
            x + (size_t)(b2 < 0 ? 0 : b2) * CHI * D;

        if (it > 0) softmax_to_smem(b2, s_alpha, warp, lane);

        const float4* __restrict__ xb14 =
            reinterpret_cast<const float4*>(xb1) + (size_t)j * 256;

        #pragma unroll 1
        for (int k = 0; k < NCG; k++) {
            // ---- phase 2 tile k (L2-hot) ----
            if (it > 0)
                p2_tile(xb2, out, b2, (j * TILES2 + k) * 256, s4, s_alpha, tid);

            // ---- phase 1 c-group k (DRAM stream, 6 coalesced loads) ----
            const float4 l = xb14[(size_t)(CHI - 1) * D4 + tid];
            float acc[CGRP];
            #pragma unroll
            for (int m = 0; m < CGRP; m++) {
                const float4 f = xb14[(size_t)(k * CGRP + m) * D4 + tid];
                acc[m] = fmaf(f.x, l.x, fmaf(f.y, l.y,
                         fmaf(f.z, l.z, f.w * l.w)));
            }
            #pragma unroll
            for (int m = 0; m < CGRP; m++) {
                #pragma unroll
                for (int o = 16; o; o >>= 1)
                    acc[m] += __shfl_xor_sync(0xFFFFFFFFu, acc[m], o);
            }
            if (lane == 0) {
                #pragma unroll
                for (int m = 0; m < CGRP; m++) sred[k * CGRP + m][warp] = acc[m];
            }
        }
        __syncthreads();

        // publish partials for b1
        if (tid < CHI) {
            float v = 0.0f;
            #pragma unroll
            for (int w = 0; w < 8; w++) v += sred[tid][w];
            g_partial[(b1 * CHI + tid) * GBLK + j] = v;
        }
        __threadfence();            // release partials
        __syncthreads();

        // group barrier (all blocks of group co-resident: grid 512 <= 4/SM*148)
        if (tid == 0) {
            unsigned* ctr = &g_bar[g * NITER + it];
            atomicAdd(ctr, 1u);
            while (*(volatile unsigned*)ctr < (unsigned)GBLK) __nanosleep(64);
            __threadfence();        // acquire
        }
        __syncthreads();
    }

    // epilogue: phase 2 for the last batch of this group
    {
        const int b2 = (NITER - 1) * NGROUPS + g;
        const float* __restrict__ xb2 = x + (size_t)b2 * CHI * D;
        softmax_to_smem(b2, s_alpha, warp, lane);
        #pragma unroll 1
        for (int k = 0; k < TILES2; k++)
            p2_tile(xb2, out, b2, (j * TILES2 + k) * 256, s4, s_alpha, tid);
    }
}

extern "C" void kernel_launch(void* const* d_in, const int* in_sizes, int n_in,
                              void* d_out, int out_size) {
    const float* x = (const float*)d_in[0];
    float* out = (float*)d_out;

    init_kernel<<<1, 64>>>();
    fused_kernel<<<NBLK, 256>>>(x, out);
}